// round 7
// baseline (speedup 1.0000x reference)
#include <cuda_runtime.h>
#include <cuda_bf16.h>
#include <cstdint>
#include <cstddef>

// Shapes are fixed by the problem: B=32, S=2048, E=D=1024.
#define BATCH 32
#define SEQ   2048
#define EDIM  1024
#define NROWS (BATCH * SEQ)   // 65536

// ---------------- scratch (static __device__ — no allocation allowed) ----------------
__device__ __nv_bfloat16 g_Ahi[(size_t)NROWS * EDIM];   // 128 MB  enc hi
__device__ __nv_bfloat16 g_Alo[(size_t)NROWS * EDIM];   // 128 MB  enc lo
__device__ __nv_bfloat16 g_Bhi[(size_t)EDIM * EDIM];    // w1^T hi  [n=e][k=d]
__device__ __nv_bfloat16 g_Blo[(size_t)EDIM * EDIM];    // w1^T lo
__device__ float g_q[BATCH * EDIM];                     // q = dec@w2 + b2 + b1
__device__ float g_scores[NROWS];
__device__ float g_attn[NROWS];

// ---------------- kernel 1: split enc fp32 -> (hi, lo) bf16 ----------------
__global__ void split_enc_kernel(const float* __restrict__ x) {
    const int n4 = NROWS * EDIM / 4;
    for (int idx = blockIdx.x * blockDim.x + threadIdx.x; idx < n4;
         idx += gridDim.x * blockDim.x) {
        float4 v = reinterpret_cast<const float4*>(x)[idx];
        __nv_bfloat16 h0 = __float2bfloat16(v.x);
        __nv_bfloat16 h1 = __float2bfloat16(v.y);
        __nv_bfloat16 h2 = __float2bfloat16(v.z);
        __nv_bfloat16 h3 = __float2bfloat16(v.w);
        __nv_bfloat16 l0 = __float2bfloat16(v.x - __bfloat162float(h0));
        __nv_bfloat16 l1 = __float2bfloat16(v.y - __bfloat162float(h1));
        __nv_bfloat16 l2 = __float2bfloat16(v.z - __bfloat162float(h2));
        __nv_bfloat16 l3 = __float2bfloat16(v.w - __bfloat162float(h3));
        __nv_bfloat162 hh0; hh0.x = h0; hh0.y = h1;
        __nv_bfloat162 hh1; hh1.x = h2; hh1.y = h3;
        __nv_bfloat162 ll0; ll0.x = l0; ll0.y = l1;
        __nv_bfloat162 ll1; ll1.x = l2; ll1.y = l3;
        __nv_bfloat162* Hp = reinterpret_cast<__nv_bfloat162*>(g_Ahi) + idx * 2;
        __nv_bfloat162* Lp = reinterpret_cast<__nv_bfloat162*>(g_Alo) + idx * 2;
        Hp[0] = hh0; Hp[1] = hh1;
        Lp[0] = ll0; Lp[1] = ll1;
    }
}

// ---------------- kernel 2: transpose + split w1 -> Bhi/Blo [n][k] ----------------
__global__ void split_w1_kernel(const float* __restrict__ w1) {
    int idx = blockIdx.x * blockDim.x + threadIdx.x;   // over 1<<20
    int nn = idx >> 10;      // output col e  -> B row
    int kk = idx & 1023;     // input dim d   -> B col
    float x = w1[(kk << 10) + nn];
    __nv_bfloat16 h = __float2bfloat16(x);
    g_Bhi[idx] = h;
    g_Blo[idx] = __float2bfloat16(x - __bfloat162float(h));
}

// ---------------- kernel 3: query projection q[b][e] = dec[b]@w2 + b2 + b1 ----------------
__global__ void query_kernel(const float* __restrict__ dec,
                             const float* __restrict__ w2,
                             const float* __restrict__ b2,
                             const float* __restrict__ b1) {
    const int b = blockIdx.y;
    const int t = threadIdx.x;
    const int e = blockIdx.x * 256 + t;
    __shared__ float sd[EDIM];
    for (int i = t; i < EDIM; i += 256) sd[i] = dec[b * EDIM + i];
    __syncthreads();
    float acc = b2[e] + b1[e];
#pragma unroll 8
    for (int d = 0; d < EDIM; ++d) acc += sd[d] * w2[(d << 10) + e];
    g_q[b * EDIM + e] = acc;
}

// ---------------- kernel 4: fused split-bf16 GEMM + tanh·v reduction -> scores ----------------
#define LDSM4(R0, R1, R2, R3, addr)                                              \
    asm volatile("ldmatrix.sync.aligned.m8n8.x4.shared.b16 {%0,%1,%2,%3}, [%4];" \
                 : "=r"(R0), "=r"(R1), "=r"(R2), "=r"(R3) : "r"(addr))

#define MMA16816(d, a, b0r, b1r)                                                  \
    asm volatile("mma.sync.aligned.m16n8k16.row.col.f32.bf16.bf16.f32 "           \
                 "{%0,%1,%2,%3}, {%4,%5,%6,%7}, {%8,%9}, {%0,%1,%2,%3};"          \
                 : "+f"((d)[0]), "+f"((d)[1]), "+f"((d)[2]), "+f"((d)[3])         \
                 : "r"((a)[0]), "r"((a)[1]), "r"((a)[2]), "r"((a)[3]),            \
                   "r"(b0r), "r"(b1r))

// Block tile: 64 rows (m) x 256 cols (n) per pass, 4 passes over n=1024.
// K segments: (Ahi,Bhi), (Alo,Bhi), (Ahi,Blo)  => K_eff = 3072.
// 8 warps as 2(m) x 4(n); warp tile 32x64 via m16n8k16.
__global__ void __launch_bounds__(256) scores_kernel(const float* __restrict__ v) {
    const int tid  = threadIdx.x;
    const int lane = tid & 31;
    const int wid  = tid >> 5;
    const int warp_m = wid >> 2;   // 0..1
    const int warp_n = wid & 3;    // 0..3
    const int row0 = blockIdx.x * 64;
    const int b    = row0 >> 11;   // row0 / 2048
    const float* qb = g_q + (b << 10);

    __shared__ __nv_bfloat16 As[64][40];    // 40-halves stride: conflict-free ldmatrix
    __shared__ __nv_bfloat16 Bs[256][40];
    __shared__ float s_acc[64];
    if (tid < 64) s_acc[tid] = 0.0f;

    const unsigned a_base = (unsigned)__cvta_generic_to_shared(
        &As[warp_m * 32 + (lane & 15)][(lane >> 4) << 3]);
    const unsigned b_base = (unsigned)__cvta_generic_to_shared(
        &Bs[warp_n * 64 + ((lane >> 4) << 3) + (lane & 7)][((lane >> 3) & 1) << 3]);

    const int ar  = tid >> 2;          // A smem row this thread fills
    const int acq = (tid & 3) << 3;    // A smem col (halves)

    for (int np = 0; np < 4; ++np) {
        float acc[16][4];
#pragma unroll
        for (int i = 0; i < 16; ++i) {
            acc[i][0] = 0.f; acc[i][1] = 0.f; acc[i][2] = 0.f; acc[i][3] = 0.f;
        }
        const int nbase = np << 8;

#pragma unroll 1
        for (int seg = 0; seg < 3; ++seg) {
            const __nv_bfloat16* __restrict__ Ap = (seg == 1) ? g_Alo : g_Ahi;
            const __nv_bfloat16* __restrict__ Bp = (seg == 2) ? g_Blo : g_Bhi;
#pragma unroll 1
            for (int k0 = 0; k0 < 1024; k0 += 32) {
                __syncthreads();
                // stage A: 64 x 32 halves (one uint4 per thread)
                *reinterpret_cast<uint4*>(&As[ar][acq]) =
                    *reinterpret_cast<const uint4*>(
                        Ap + (((size_t)(row0 + ar)) << 10) + k0 + acq);
                // stage B: 256 x 32 halves (four uint4 per thread)
#pragma unroll
                for (int j = 0; j < 4; ++j) {
                    int idx = tid + (j << 8);
                    int nr = idx >> 2;
                    int cq = (idx & 3) << 3;
                    *reinterpret_cast<uint4*>(&Bs[nr][cq]) =
                        *reinterpret_cast<const uint4*>(
                            Bp + (((size_t)(nbase + nr)) << 10) + k0 + cq);
                }
                __syncthreads();

#pragma unroll
                for (int kk = 0; kk < 2; ++kk) {   // two k16 steps
                    uint32_t a0[4], a1[4];
                    LDSM4(a0[0], a0[1], a0[2], a0[3], a_base + kk * 32);
                    LDSM4(a1[0], a1[1], a1[2], a1[3], a_base + 1280 + kk * 32);
#pragma unroll
                    for (int p = 0; p < 4; ++p) {  // nf pairs
                        uint32_t bb0, bb1, bb2, bb3;
                        LDSM4(bb0, bb1, bb2, bb3, b_base + p * 1280 + kk * 32);
                        MMA16816(acc[(p << 1)],         a0, bb0, bb1);
                        MMA16816(acc[(p << 1) + 1],     a0, bb2, bb3);
                        MMA16816(acc[8 + (p << 1)],     a1, bb0, bb1);
                        MMA16816(acc[8 + (p << 1) + 1], a1, bb2, bb3);
                    }
                }
            }
        }

        // fused epilogue: score_part[row] += sum_n tanh(C + q) * v
        float part[4] = {0.f, 0.f, 0.f, 0.f};
        const int ncol0 = nbase + warp_n * 64 + ((lane & 3) << 1);
#pragma unroll
        for (int mf = 0; mf < 2; ++mf) {
#pragma unroll
            for (int nf = 0; nf < 8; ++nf) {
                int n = ncol0 + (nf << 3);
                float q0 = qb[n], q1 = qb[n + 1];
                float v0 = v[n],  v1 = v[n + 1];
                const float* c = acc[mf * 8 + nf];
                part[mf * 2 + 0] += tanhf(c[0] + q0) * v0 + tanhf(c[1] + q1) * v1;
                part[mf * 2 + 1] += tanhf(c[2] + q0) * v0 + tanhf(c[3] + q1) * v1;
            }
        }
        const int rb = warp_m * 32 + (lane >> 2);
        atomicAdd(&s_acc[rb],      part[0]);
        atomicAdd(&s_acc[rb + 8],  part[1]);
        atomicAdd(&s_acc[rb + 16], part[2]);
        atomicAdd(&s_acc[rb + 24], part[3]);
    }

    __syncthreads();
    if (tid < 64) g_scores[row0 + tid] = s_acc[tid];   // +bv dropped: softmax-invariant
}

// ---------------- kernel 5: softmax over S per batch ----------------
__global__ void softmax_kernel() {
    const int b = blockIdx.x;
    const int t = threadIdx.x;
    __shared__ float red[256];
    const float* sc = g_scores + b * SEQ;
    float* at = g_attn + b * SEQ;

    float m = -1e30f;
    for (int i = t; i < SEQ; i += 256) m = fmaxf(m, sc[i]);
    red[t] = m; __syncthreads();
#pragma unroll
    for (int o = 128; o > 0; o >>= 1) {
        if (t < o) red[t] = fmaxf(red[t], red[t + o]);
        __syncthreads();
    }
    float mx = red[0];
    __syncthreads();

    float s = 0.f;
    for (int i = t; i < SEQ; i += 256) {
        float e = expf(sc[i] - mx);
        at[i] = e;
        s += e;
    }
    red[t] = s; __syncthreads();
#pragma unroll
    for (int o = 128; o > 0; o >>= 1) {
        if (t < o) red[t] += red[t + o];
        __syncthreads();
    }
    float inv = 1.0f / red[0];
    for (int i = t; i < SEQ; i += 256) at[i] *= inv;
}

// ---------------- kernel 6: context[b][e] = sum_s attn * enc ----------------
__global__ void context_kernel(const float* __restrict__ enc, float* __restrict__ out) {
    const int b = blockIdx.y;
    const int chunk = blockIdx.x;      // 4 chunks of 256 e
    const int t = threadIdx.x;
    const int sub = t >> 6;            // 4 s-partitions
    const int tt = t & 63;

    __shared__ float sa[SEQ];
    __shared__ float4 part[3][64];
    for (int i = t; i < SEQ; i += 256) sa[i] = g_attn[b * SEQ + i];
    __syncthreads();

    const float4* ep = reinterpret_cast<const float4*>(enc) +
                       (size_t)b * SEQ * 256 + chunk * 64 + tt;
    float4 acc = {0.f, 0.f, 0.f, 0.f};
    const int s0 = sub * 512;
#pragma unroll 8
    for (int s = s0; s < s0 + 512; ++s) {
        float a = sa[s];
        float4 x = ep[(size_t)s * 256];
        acc.x += a * x.x; acc.y += a * x.y; acc.z += a * x.z; acc.w += a * x.w;
    }
    if (sub) part[sub - 1][tt] = acc;
    __syncthreads();
    if (sub == 0) {
#pragma unroll
        for (int j = 0; j < 3; ++j) {
            float4 p = part[j][tt];
            acc.x += p.x; acc.y += p.y; acc.z += p.z; acc.w += p.w;
        }
        reinterpret_cast<float4*>(out)[b * 256 + chunk * 64 + tt] = acc;
    }
}

// ---------------- launch ----------------
extern "C" void kernel_launch(void* const* d_in, const int* in_sizes, int n_in,
                              void* d_out, int out_size) {
    const float* enc = (const float*)d_in[0];   // [32,2048,1024]
    const float* dec = (const float*)d_in[1];   // [32,1,1024]
    const float* w1  = (const float*)d_in[2];   // [1024,1024]
    const float* b1  = (const float*)d_in[3];   // [1024]
    const float* w2  = (const float*)d_in[4];   // [1024,1024]
    const float* b2  = (const float*)d_in[5];   // [1024]
    const float* v   = (const float*)d_in[6];   // [1024,1]
    // d_in[7] = bv: softmax-invariant, unused.
    float* out = (float*)d_out;                 // [32,1024]

    split_enc_kernel<<<8192, 256>>>(enc);
    split_w1_kernel<<<(EDIM * EDIM) / 256, 256>>>(w1);
    query_kernel<<<dim3(4, BATCH), 256>>>(dec, w2, b2, b1);
    scores_kernel<<<NROWS / 64, 256>>>(v);
    softmax_kernel<<<BATCH, 256>>>();
    context_kernel<<<dim3(4, BATCH), 256>>>(enc, out);
}

// round 9
// speedup vs baseline: 1.3796x; 1.3796x over previous
#include <cuda_runtime.h>
#include <cuda_fp16.h>
#include <cstdint>
#include <cstddef>

// Shapes fixed by the problem: B=32, S=2048, E=D=1024.
#define BATCH 32
#define SEQ   2048
#define EDIM  1024
#define NROWS (BATCH * SEQ)   // 65536

// ---------------- scratch (static __device__ — no allocation allowed) ----------------
__device__ __half g_Ahi[(size_t)NROWS * EDIM];   // 128 MB  enc hi (fp16)
__device__ __half g_Alo[(size_t)NROWS * EDIM];   // 128 MB  enc lo (fp16)
__device__ __half g_Bh [(size_t)EDIM * EDIM];    // w1^T fp16  [n=e][k=d]
__device__ float g_q[BATCH * EDIM];              // q = dec@w2 + b2 + b1
__device__ float g_scores[NROWS];
__device__ float g_attn[NROWS];

// ---------------- kernel 1: split enc fp32 -> (hi, lo) fp16 ----------------
__global__ void split_enc_kernel(const float* __restrict__ x) {
    const int n4 = NROWS * EDIM / 4;
    for (int idx = blockIdx.x * blockDim.x + threadIdx.x; idx < n4;
         idx += gridDim.x * blockDim.x) {
        float4 v = reinterpret_cast<const float4*>(x)[idx];
        __half h0 = __float2half(v.x);
        __half h1 = __float2half(v.y);
        __half h2 = __float2half(v.z);
        __half h3 = __float2half(v.w);
        __half l0 = __float2half(v.x - __half2float(h0));
        __half l1 = __float2half(v.y - __half2float(h1));
        __half l2 = __float2half(v.z - __half2float(h2));
        __half l3 = __float2half(v.w - __half2float(h3));
        __half2* Hp = reinterpret_cast<__half2*>(g_Ahi) + idx * 2;
        __half2* Lp = reinterpret_cast<__half2*>(g_Alo) + idx * 2;
        Hp[0] = __halves2half2(h0, h1);
        Hp[1] = __halves2half2(h2, h3);
        Lp[0] = __halves2half2(l0, l1);
        Lp[1] = __halves2half2(l2, l3);
    }
}

// ---------------- kernel 2: transpose w1 -> Bh [n][k] fp16 ----------------
__global__ void split_w1_kernel(const float* __restrict__ w1) {
    int idx = blockIdx.x * blockDim.x + threadIdx.x;   // over 1<<20
    int nn = idx >> 10;      // output col e  -> B row
    int kk = idx & 1023;     // input dim d   -> B col
    g_Bh[idx] = __float2half(w1[(kk << 10) + nn]);
}

// ---------------- kernel 3: query projection q[b][e] = dec[b]@w2 + b2 + b1 ----------------
__global__ void query_kernel(const float* __restrict__ dec,
                             const float* __restrict__ w2,
                             const float* __restrict__ b2,
                             const float* __restrict__ b1) {
    const int b = blockIdx.y;
    const int t = threadIdx.x;
    const int e = blockIdx.x * 256 + t;
    __shared__ float sd[EDIM];
    for (int i = t; i < EDIM; i += 256) sd[i] = dec[b * EDIM + i];
    __syncthreads();
    float acc = b2[e] + b1[e];
#pragma unroll 8
    for (int d = 0; d < EDIM; ++d) acc += sd[d] * w2[(d << 10) + e];
    g_q[b * EDIM + e] = acc;
}

// ---------------- kernel 4: pipelined split-fp16 GEMM + fused tanh·v -> scores ----------
#define LDSM4(R0, R1, R2, R3, addr)                                              \
    asm volatile("ldmatrix.sync.aligned.m8n8.x4.shared.b16 {%0,%1,%2,%3}, [%4];" \
                 : "=r"(R0), "=r"(R1), "=r"(R2), "=r"(R3) : "r"(addr))

#define MMA16816(d, a, b0r, b1r)                                                  \
    asm volatile("mma.sync.aligned.m16n8k16.row.col.f32.f16.f16.f32 "             \
                 "{%0,%1,%2,%3}, {%4,%5,%6,%7}, {%8,%9}, {%0,%1,%2,%3};"          \
                 : "+f"((d)[0]), "+f"((d)[1]), "+f"((d)[2]), "+f"((d)[3])         \
                 : "r"((a)[0]), "r"((a)[1]), "r"((a)[2]), "r"((a)[3]),            \
                   "r"(b0r), "r"(b1r))

#define CP_ASYNC16(dst, src)                                                     \
    asm volatile("cp.async.cg.shared.global [%0], [%1], 16;" :: "r"(dst), "l"(src))
#define CP_COMMIT() asm volatile("cp.async.commit_group;" ::: "memory")
#define CP_WAIT2()  asm volatile("cp.async.wait_group 2;" ::: "memory")

// SMEM ring: 4 stages x (A 128x40h + B 128x40h) = 4 x 20480 B, then q, v, s_acc
#define STG_BYTES 20480
#define OFF_Q 81920
#define OFF_V 86016
#define OFF_ACC 90112
#define SMEM_TOTAL 90624

// CTA tile m=128 x n=128 (8 n-chunks over N=1024); 8 warps = 4m x 2n, warp 32x64.
// K stream per n-chunk: 2 segments {Ahi·Bh, Alo·Bh} x 32 chunks of k=32 halves.
// Flat stream: 8 np * 64 = 512 chunks, 4-stage cp.async pipeline across all of it.
__global__ void __launch_bounds__(256) scores_kernel(const float* __restrict__ v) {
    extern __shared__ char smem[];
    uint32_t sb;
    asm("{ .reg .u64 t; cvta.to.shared.u64 t, %1; cvt.u32.u64 %0, t; }"
        : "=r"(sb) : "l"(smem));

    const int tid  = threadIdx.x;
    const int lane = tid & 31;
    const int wid  = tid >> 5;
    const int wm   = wid >> 1;   // 0..3
    const int wn   = wid & 1;    // 0..1
    const int row0 = blockIdx.x << 7;
    const int b    = row0 >> 11;

    float* s_q   = reinterpret_cast<float*>(smem + OFF_Q);
    float* s_v   = reinterpret_cast<float*>(smem + OFF_V);
    float* s_acc = reinterpret_cast<float*>(smem + OFF_ACC);

    for (int i = tid; i < EDIM; i += 256) {
        s_q[i] = g_q[(b << 10) + i];
        s_v[i] = v[i];
    }
    if (tid < 128) s_acc[tid] = 0.0f;

    // per-thread intra-tile ldmatrix offsets (row stride 80 B)
    const uint32_t a_off = (uint32_t)((wm * 32 + (lane & 15)) * 80 + ((lane >> 4) << 4));
    const uint32_t b_off = (uint32_t)((wn * 64 + ((lane >> 4) << 3) + (lane & 7)) * 80 +
                                      (((lane >> 3) & 1) << 4));
    // per-thread staging slots: 2 for A, 2 for B
    const int sr0 = tid >> 2,        sg0 = tid & 3;          // slot tid
    const int sr1 = (tid + 256) >> 2, sg1 = (tid + 256) & 3; // slot tid+256

    // issue cp.asyncs for flat chunk `it`
    auto stage = [&](int it) {
        const int np  = it >> 6;
        const int r   = it & 63;
        const int seg = r >> 5;
        const int k0  = (r & 31) << 5;        // halves
        const __half* __restrict__ Ap = seg ? g_Alo : g_Ahi;
        const uint32_t abase = sb + (uint32_t)(it & 3) * STG_BYTES;
        const uint32_t bbase = abase + 10240;
        const int nbase = np << 7;
        CP_ASYNC16(abase + sr0 * 80 + sg0 * 16,
                   Ap + (((size_t)(row0 + sr0)) << 10) + k0 + sg0 * 8);
        CP_ASYNC16(abase + sr1 * 80 + sg1 * 16,
                   Ap + (((size_t)(row0 + sr1)) << 10) + k0 + sg1 * 8);
        CP_ASYNC16(bbase + sr0 * 80 + sg0 * 16,
                   g_Bh + (((size_t)(nbase + sr0)) << 10) + k0 + sg0 * 8);
        CP_ASYNC16(bbase + sr1 * 80 + sg1 * 16,
                   g_Bh + (((size_t)(nbase + sr1)) << 10) + k0 + sg1 * 8);
    };

    // prologue: prefetch 3 chunks
    stage(0); CP_COMMIT();
    stage(1); CP_COMMIT();
    stage(2); CP_COMMIT();

    float acc[16][4];

#pragma unroll 1
    for (int c = 0; c < 512; ++c) {
        if ((c & 63) == 0) {
#pragma unroll
            for (int i = 0; i < 16; ++i) {
                acc[i][0] = 0.f; acc[i][1] = 0.f; acc[i][2] = 0.f; acc[i][3] = 0.f;
            }
        }

        CP_WAIT2();
        __syncthreads();

        const uint32_t base = sb + (uint32_t)(c & 3) * STG_BYTES;
        const uint32_t a_addr = base + a_off;
        const uint32_t b_addr = base + 10240 + b_off;
#pragma unroll
        for (int kk = 0; kk < 2; ++kk) {
            uint32_t a0[4], a1[4];
            LDSM4(a0[0], a0[1], a0[2], a0[3], a_addr + kk * 32);
            LDSM4(a1[0], a1[1], a1[2], a1[3], a_addr + 1280 + kk * 32);
#pragma unroll
            for (int p = 0; p < 4; ++p) {
                uint32_t bb0, bb1, bb2, bb3;
                LDSM4(bb0, bb1, bb2, bb3, b_addr + p * 1280 + kk * 32);
                MMA16816(acc[(p << 1)],         a0, bb0, bb1);
                MMA16816(acc[(p << 1) + 1],     a0, bb2, bb3);
                MMA16816(acc[8 + (p << 1)],     a1, bb0, bb1);
                MMA16816(acc[8 + (p << 1) + 1], a1, bb2, bb3);
            }
        }

        if (c + 3 < 512) stage(c + 3);
        CP_COMMIT();

        if ((c & 63) == 63) {
            // epilogue for n-chunk np: score_part[row] += sum_n tanh(C + q) * v
            const int np = c >> 6;
            float part[4] = {0.f, 0.f, 0.f, 0.f};
            const int ncol0 = (np << 7) + wn * 64 + ((lane & 3) << 1);
#pragma unroll
            for (int mf = 0; mf < 2; ++mf) {
#pragma unroll
                for (int nf = 0; nf < 8; ++nf) {
                    int n = ncol0 + (nf << 3);
                    float q0 = s_q[n], q1 = s_q[n + 1];
                    float v0 = s_v[n], v1 = s_v[n + 1];
                    const float* cc = acc[mf * 8 + nf];
                    part[mf * 2 + 0] += tanhf(cc[0] + q0) * v0 + tanhf(cc[1] + q1) * v1;
                    part[mf * 2 + 1] += tanhf(cc[2] + q0) * v0 + tanhf(cc[3] + q1) * v1;
                }
            }
            const int rb = wm * 32 + (lane >> 2);
            atomicAdd(&s_acc[rb],      part[0]);
            atomicAdd(&s_acc[rb + 8],  part[1]);
            atomicAdd(&s_acc[rb + 16], part[2]);
            atomicAdd(&s_acc[rb + 24], part[3]);
        }
    }

    __syncthreads();
    if (tid < 128) g_scores[row0 + tid] = s_acc[tid];   // +bv dropped: softmax-invariant
}

// ---------------- kernel 5: softmax over S per batch ----------------
__global__ void softmax_kernel() {
    const int b = blockIdx.x;
    const int t = threadIdx.x;
    __shared__ float red[256];
    const float* sc = g_scores + b * SEQ;
    float* at = g_attn + b * SEQ;

    float m = -1e30f;
    for (int i = t; i < SEQ; i += 256) m = fmaxf(m, sc[i]);
    red[t] = m; __syncthreads();
#pragma unroll
    for (int o = 128; o > 0; o >>= 1) {
        if (t < o) red[t] = fmaxf(red[t], red[t + o]);
        __syncthreads();
    }
    float mx = red[0];
    __syncthreads();

    float s = 0.f;
    for (int i = t; i < SEQ; i += 256) {
        float e = expf(sc[i] - mx);
        at[i] = e;
        s += e;
    }
    red[t] = s; __syncthreads();
#pragma unroll
    for (int o = 128; o > 0; o >>= 1) {
        if (t < o) red[t] += red[t + o];
        __syncthreads();
    }
    float inv = 1.0f / red[0];
    for (int i = t; i < SEQ; i += 256) at[i] *= inv;
}

// ---------------- kernel 6: context[b][e] = sum_s attn * enc ----------------
__global__ void context_kernel(const float* __restrict__ enc, float* __restrict__ out) {
    const int b = blockIdx.y;
    const int chunk = blockIdx.x;      // 4 chunks of 256 e
    const int t = threadIdx.x;
    const int sub = t >> 6;            // 4 s-partitions
    const int tt = t & 63;

    __shared__ float sa[SEQ];
    __shared__ float4 part[3][64];
    for (int i = t; i < SEQ; i += 256) sa[i] = g_attn[b * SEQ + i];
    __syncthreads();

    const float4* ep = reinterpret_cast<const float4*>(enc) +
                       (size_t)b * SEQ * 256 + chunk * 64 + tt;
    float4 acc = {0.f, 0.f, 0.f, 0.f};
    const int s0 = sub * 512;
#pragma unroll 8
    for (int s = s0; s < s0 + 512; ++s) {
        float a = sa[s];
        float4 x = ep[(size_t)s * 256];
        acc.x += a * x.x; acc.y += a * x.y; acc.z += a * x.z; acc.w += a * x.w;
    }
    if (sub) part[sub - 1][tt] = acc;
    __syncthreads();
    if (sub == 0) {
#pragma unroll
        for (int j = 0; j < 3; ++j) {
            float4 p = part[j][tt];
            acc.x += p.x; acc.y += p.y; acc.z += p.z; acc.w += p.w;
        }
        reinterpret_cast<float4*>(out)[b * 256 + chunk * 64 + tt] = acc;
    }
}

// ---------------- launch ----------------
extern "C" void kernel_launch(void* const* d_in, const int* in_sizes, int n_in,
                              void* d_out, int out_size) {
    const float* enc = (const float*)d_in[0];   // [32,2048,1024]
    const float* dec = (const float*)d_in[1];   // [32,1,1024]
    const float* w1  = (const float*)d_in[2];   // [1024,1024]
    const float* b1  = (const float*)d_in[3];   // [1024]
    const float* w2  = (const float*)d_in[4];   // [1024,1024]
    const float* b2  = (const float*)d_in[5];   // [1024]
    const float* v   = (const float*)d_in[6];   // [1024,1]
    // d_in[7] = bv: softmax-invariant, unused.
    float* out = (float*)d_out;                 // [32,1024]

    cudaFuncSetAttribute(scores_kernel,
                         cudaFuncAttributeMaxDynamicSharedMemorySize, SMEM_TOTAL);

    split_enc_kernel<<<8192, 256>>>(enc);
    split_w1_kernel<<<(EDIM * EDIM) / 256, 256>>>(w1);
    query_kernel<<<dim3(4, BATCH), 256>>>(dec, w2, b2, b1);
    scores_kernel<<<NROWS / 128, 256, SMEM_TOTAL>>>(v);
    softmax_kernel<<<BATCH, 256>>>();
    context_kernel<<<dim3(4, BATCH), 256>>>(enc, out);
}

// round 11
// speedup vs baseline: 2.1873x; 1.5854x over previous
#include <cuda_runtime.h>
#include <cuda_fp16.h>
#include <cstdint>
#include <cstddef>

// Shapes fixed by the problem: B=32, S=2048, E=D=1024.
#define BATCH 32
#define SEQ   2048
#define EDIM  1024
#define NROWS (BATCH * SEQ)   // 65536

// ---------------- scratch (static __device__ — no allocation allowed) ----------------
__device__ __half g_Ahi[(size_t)NROWS * EDIM];   // 128 MB  enc hi (fp16)
__device__ __half g_Alo[(size_t)NROWS * EDIM];   // 128 MB  enc lo (fp16)
__device__ __half g_Bh [(size_t)EDIM * EDIM];    // w1^T fp16  [n=e][k=d]
__device__ float g_q[BATCH * EDIM];              // q = dec@w2 + b2 + b1
__device__ float g_scores[NROWS];
__device__ float g_attn[NROWS];

// ---------------- kernel 1: split enc fp32 -> (hi, lo) fp16 ----------------
__global__ void split_enc_kernel(const float* __restrict__ x) {
    const int n4 = NROWS * EDIM / 4;
    for (int idx = blockIdx.x * blockDim.x + threadIdx.x; idx < n4;
         idx += gridDim.x * blockDim.x) {
        float4 v = reinterpret_cast<const float4*>(x)[idx];
        __half h0 = __float2half(v.x);
        __half h1 = __float2half(v.y);
        __half h2 = __float2half(v.z);
        __half h3 = __float2half(v.w);
        __half l0 = __float2half(v.x - __half2float(h0));
        __half l1 = __float2half(v.y - __half2float(h1));
        __half l2 = __float2half(v.z - __half2float(h2));
        __half l3 = __float2half(v.w - __half2float(h3));
        __half2* Hp = reinterpret_cast<__half2*>(g_Ahi) + idx * 2;
        __half2* Lp = reinterpret_cast<__half2*>(g_Alo) + idx * 2;
        Hp[0] = __halves2half2(h0, h1);
        Hp[1] = __halves2half2(h2, h3);
        Lp[0] = __halves2half2(l0, l1);
        Lp[1] = __halves2half2(l2, l3);
    }
}

// ---------------- kernel 2: transpose w1 -> Bh [n][k] fp16 ----------------
__global__ void split_w1_kernel(const float* __restrict__ w1) {
    int idx = blockIdx.x * blockDim.x + threadIdx.x;   // over 1<<20
    int nn = idx >> 10;      // output col e  -> B row
    int kk = idx & 1023;     // input dim d   -> B col
    g_Bh[idx] = __float2half(w1[(kk << 10) + nn]);
}

// ---------------- kernel 3: query projection q[b][e] = dec[b]@w2 + b2 + b1 ----------------
__global__ void query_kernel(const float* __restrict__ dec,
                             const float* __restrict__ w2,
                             const float* __restrict__ b2,
                             const float* __restrict__ b1) {
    const int b = blockIdx.y;
    const int t = threadIdx.x;
    const int e = blockIdx.x * 256 + t;
    __shared__ float sd[EDIM];
    for (int i = t; i < EDIM; i += 256) sd[i] = dec[b * EDIM + i];
    __syncthreads();
    float acc = b2[e] + b1[e];
#pragma unroll 8
    for (int d = 0; d < EDIM; ++d) acc += sd[d] * w2[(d << 10) + e];
    g_q[b * EDIM + e] = acc;
}

// ---------------- kernel 4: pipelined split-fp16 GEMM + fused tanh·v -> scores ----------
#define LDSM4(R0, R1, R2, R3, addr)                                              \
    asm volatile("ldmatrix.sync.aligned.m8n8.x4.shared.b16 {%0,%1,%2,%3}, [%4];" \
                 : "=r"(R0), "=r"(R1), "=r"(R2), "=r"(R3) : "r"(addr))

#define MMA16816(d, a, b0r, b1r)                                                  \
    asm volatile("mma.sync.aligned.m16n8k16.row.col.f32.f16.f16.f32 "             \
                 "{%0,%1,%2,%3}, {%4,%5,%6,%7}, {%8,%9}, {%0,%1,%2,%3};"          \
                 : "+f"((d)[0]), "+f"((d)[1]), "+f"((d)[2]), "+f"((d)[3])         \
                 : "r"((a)[0]), "r"((a)[1]), "r"((a)[2]), "r"((a)[3]),            \
                   "r"(b0r), "r"(b1r))

#define CP_ASYNC16(dst, src)                                                     \
    asm volatile("cp.async.cg.shared.global [%0], [%1], 16;" :: "r"(dst), "l"(src))
#define CP_COMMIT() asm volatile("cp.async.commit_group;" ::: "memory")
#define CP_WAIT1()  asm volatile("cp.async.wait_group 1;" ::: "memory")

// Chunk = (np, k0): three tiles {Ahi 128x32h, Alo 128x32h, B 128x32h}, rows padded to 80B.
// 3-stage ring: stage = 3 * 10240 = 30720 B.  256 chunks = 8 np * 32 k-chunks.
#define TILE_BYTES 10240
#define STG_BYTES  30720
#define OFF_Q   92160
#define OFF_V   96256
#define OFF_ACC 100352
#define SMEM_TOTAL 100864

__global__ void __launch_bounds__(256, 2) scores_kernel(const float* __restrict__ v) {
    extern __shared__ char smem[];
    uint32_t sb;
    asm("{ .reg .u64 t; cvta.to.shared.u64 t, %1; cvt.u32.u64 %0, t; }"
        : "=r"(sb) : "l"(smem));

    const int tid  = threadIdx.x;
    const int lane = tid & 31;
    const int wid  = tid >> 5;
    const int wm   = wid >> 1;   // 0..3
    const int wn   = wid & 1;    // 0..1
    const int row0 = blockIdx.x << 7;
    const int b    = row0 >> 11;

    float* s_q   = reinterpret_cast<float*>(smem + OFF_Q);
    float* s_v   = reinterpret_cast<float*>(smem + OFF_V);
    float* s_acc = reinterpret_cast<float*>(smem + OFF_ACC);

    for (int i = tid; i < EDIM; i += 256) {
        s_q[i] = g_q[(b << 10) + i];
        s_v[i] = v[i];
    }
    if (tid < 128) s_acc[tid] = 0.0f;

    // per-thread intra-tile ldmatrix offsets (row stride 80 B)
    const uint32_t a_off = (uint32_t)((wm * 32 + (lane & 15)) * 80 + ((lane >> 4) << 4));
    const uint32_t b_off = (uint32_t)((wn * 64 + ((lane >> 4) << 3) + (lane & 7)) * 80 +
                                      (((lane >> 3) & 1) << 4));
    // per-thread staging slots (tile = 512 uint4): slots tid and tid+256
    const int sr0 = tid >> 2,         sg0 = tid & 3;
    const int sr1 = (tid + 256) >> 2, sg1 = (tid + 256) & 3;

    // issue cp.asyncs for chunk `it`: Ahi, Alo, B tiles into ring buffer it%3
    auto stage = [&](int it) {
        const int np = it >> 5;
        const int k0 = (it & 31) << 5;        // halves
        const uint32_t base = sb + (uint32_t)(it % 3) * STG_BYTES;
        const int nbase = np << 7;
        const size_t arow0 = ((size_t)(row0 + sr0)) << 10;
        const size_t arow1 = ((size_t)(row0 + sr1)) << 10;
        CP_ASYNC16(base + sr0 * 80 + sg0 * 16,               g_Ahi + arow0 + k0 + sg0 * 8);
        CP_ASYNC16(base + sr1 * 80 + sg1 * 16,               g_Ahi + arow1 + k0 + sg1 * 8);
        CP_ASYNC16(base + TILE_BYTES + sr0 * 80 + sg0 * 16,  g_Alo + arow0 + k0 + sg0 * 8);
        CP_ASYNC16(base + TILE_BYTES + sr1 * 80 + sg1 * 16,  g_Alo + arow1 + k0 + sg1 * 8);
        CP_ASYNC16(base + 2 * TILE_BYTES + sr0 * 80 + sg0 * 16,
                   g_Bh + (((size_t)(nbase + sr0)) << 10) + k0 + sg0 * 8);
        CP_ASYNC16(base + 2 * TILE_BYTES + sr1 * 80 + sg1 * 16,
                   g_Bh + (((size_t)(nbase + sr1)) << 10) + k0 + sg1 * 8);
    };

    // prologue: prefetch 2 chunks
    stage(0); CP_COMMIT();
    stage(1); CP_COMMIT();

    float acc[16][4];

#pragma unroll 1
    for (int c = 0; c < 256; ++c) {
        if ((c & 31) == 0) {
#pragma unroll
            for (int i = 0; i < 16; ++i) {
                acc[i][0] = 0.f; acc[i][1] = 0.f; acc[i][2] = 0.f; acc[i][3] = 0.f;
            }
        }

        CP_WAIT1();
        __syncthreads();

        const uint32_t base   = sb + (uint32_t)(c % 3) * STG_BYTES;
        const uint32_t ah_addr = base + a_off;
        const uint32_t al_addr = base + TILE_BYTES + a_off;
        const uint32_t b_addr  = base + 2 * TILE_BYTES + b_off;
#pragma unroll
        for (int kk = 0; kk < 2; ++kk) {
            uint32_t a0h[4], a1h[4], a0l[4], a1l[4];
            LDSM4(a0h[0], a0h[1], a0h[2], a0h[3], ah_addr + kk * 32);
            LDSM4(a1h[0], a1h[1], a1h[2], a1h[3], ah_addr + 1280 + kk * 32);
            LDSM4(a0l[0], a0l[1], a0l[2], a0l[3], al_addr + kk * 32);
            LDSM4(a1l[0], a1l[1], a1l[2], a1l[3], al_addr + 1280 + kk * 32);
#pragma unroll
            for (int p = 0; p < 4; ++p) {
                uint32_t bb0, bb1, bb2, bb3;
                LDSM4(bb0, bb1, bb2, bb3, b_addr + p * 1280 + kk * 32);
                MMA16816(acc[(p << 1)],         a0h, bb0, bb1);
                MMA16816(acc[(p << 1) + 1],     a0h, bb2, bb3);
                MMA16816(acc[8 + (p << 1)],     a1h, bb0, bb1);
                MMA16816(acc[8 + (p << 1) + 1], a1h, bb2, bb3);
                MMA16816(acc[(p << 1)],         a0l, bb0, bb1);
                MMA16816(acc[(p << 1) + 1],     a0l, bb2, bb3);
                MMA16816(acc[8 + (p << 1)],     a1l, bb0, bb1);
                MMA16816(acc[8 + (p << 1) + 1], a1l, bb2, bb3);
            }
        }

        if (c + 2 < 256) { stage(c + 2); }
        CP_COMMIT();

        if ((c & 31) == 31) {
            // epilogue for n-chunk np: score_part[row] += sum_n tanh(C + q) * v
            const int np = c >> 5;
            float part[4] = {0.f, 0.f, 0.f, 0.f};
            const int ncol0 = (np << 7) + wn * 64 + ((lane & 3) << 1);
#pragma unroll
            for (int mf = 0; mf < 2; ++mf) {
#pragma unroll
                for (int nf = 0; nf < 8; ++nf) {
                    int n = ncol0 + (nf << 3);
                    float q0 = s_q[n], q1 = s_q[n + 1];
                    float v0 = s_v[n], v1 = s_v[n + 1];
                    const float* cc = acc[mf * 8 + nf];
                    part[mf * 2 + 0] += tanhf(cc[0] + q0) * v0 + tanhf(cc[1] + q1) * v1;
                    part[mf * 2 + 1] += tanhf(cc[2] + q0) * v0 + tanhf(cc[3] + q1) * v1;
                }
            }
            const int rb = wm * 32 + (lane >> 2);
            atomicAdd(&s_acc[rb],      part[0]);
            atomicAdd(&s_acc[rb + 8],  part[1]);
            atomicAdd(&s_acc[rb + 16], part[2]);
            atomicAdd(&s_acc[rb + 24], part[3]);
        }
    }

    __syncthreads();
    if (tid < 128) g_scores[row0 + tid] = s_acc[tid];   // +bv dropped: softmax-invariant
}

// ---------------- kernel 5: softmax over S per batch ----------------
__global__ void softmax_kernel() {
    const int b = blockIdx.x;
    const int t = threadIdx.x;
    __shared__ float red[256];
    const float* sc = g_scores + b * SEQ;
    float* at = g_attn + b * SEQ;

    float m = -1e30f;
    for (int i = t; i < SEQ; i += 256) m = fmaxf(m, sc[i]);
    red[t] = m; __syncthreads();
#pragma unroll
    for (int o = 128; o > 0; o >>= 1) {
        if (t < o) red[t] = fmaxf(red[t], red[t + o]);
        __syncthreads();
    }
    float mx = red[0];
    __syncthreads();

    float s = 0.f;
    for (int i = t; i < SEQ; i += 256) {
        float e = expf(sc[i] - mx);
        at[i] = e;
        s += e;
    }
    red[t] = s; __syncthreads();
#pragma unroll
    for (int o = 128; o > 0; o >>= 1) {
        if (t < o) red[t] += red[t + o];
        __syncthreads();
    }
    float inv = 1.0f / red[0];
    for (int i = t; i < SEQ; i += 256) at[i] *= inv;
}

// ---------------- kernel 6: context[b][e] = sum_s attn * enc ----------------
__global__ void context_kernel(const float* __restrict__ enc, float* __restrict__ out) {
    const int b = blockIdx.y;
    const int chunk = blockIdx.x;      // 4 chunks of 256 e
    const int t = threadIdx.x;
    const int sub = t >> 6;            // 4 s-partitions
    const int tt = t & 63;

    __shared__ float sa[SEQ];
    __shared__ float4 part[3][64];
    for (int i = t; i < SEQ; i += 256) sa[i] = g_attn[b * SEQ + i];
    __syncthreads();

    const float4* ep = reinterpret_cast<const float4*>(enc) +
                       (size_t)b * SEQ * 256 + chunk * 64 + tt;
    float4 acc = {0.f, 0.f, 0.f, 0.f};
    const int s0 = sub * 512;
#pragma unroll 8
    for (int s = s0; s < s0 + 512; ++s) {
        float a = sa[s];
        float4 x = ep[(size_t)s * 256];
        acc.x += a * x.x; acc.y += a * x.y; acc.z += a * x.z; acc.w += a * x.w;
    }
    if (sub) part[sub - 1][tt] = acc;
    __syncthreads();
    if (sub == 0) {
#pragma unroll
        for (int j = 0; j < 3; ++j) {
            float4 p = part[j][tt];
            acc.x += p.x; acc.y += p.y; acc.z += p.z; acc.w += p.w;
        }
        reinterpret_cast<float4*>(out)[b * 256 + chunk * 64 + tt] = acc;
    }
}

// ---------------- launch ----------------
extern "C" void kernel_launch(void* const* d_in, const int* in_sizes, int n_in,
                              void* d_out, int out_size) {
    const float* enc = (const float*)d_in[0];   // [32,2048,1024]
    const float* dec = (const float*)d_in[1];   // [32,1,1024]
    const float* w1  = (const float*)d_in[2];   // [1024,1024]
    const float* b1  = (const float*)d_in[3];   // [1024]
    const float* w2  = (const float*)d_in[4];   // [1024,1024]
    const float* b2  = (const float*)d_in[5];   // [1024]
    const float* v   = (const float*)d_in[6];   // [1024,1]
    // d_in[7] = bv: softmax-invariant, unused.
    float* out = (float*)d_out;                 // [32,1024]

    cudaFuncSetAttribute(scores_kernel,
                         cudaFuncAttributeMaxDynamicSharedMemorySize, SMEM_TOTAL);

    split_enc_kernel<<<8192, 256>>>(enc);
    split_w1_kernel<<<(EDIM * EDIM) / 256, 256>>>(w1);
    query_kernel<<<dim3(4, BATCH), 256>>>(dec, w2, b2, b1);
    scores_kernel<<<NROWS / 128, 256, SMEM_TOTAL>>>(v);
    softmax_kernel<<<BATCH, 256>>>();
    context_kernel<<<dim3(4, BATCH), 256>>>(enc, out);
}